// round 9
// baseline (speedup 1.0000x reference)
#include <cuda_runtime.h>
#include <cuda_fp16.h>
#include <cstdint>

#define CH        151
#define N_EDGES   47
#define RPT       16                     // rows per warp-tile
#define TILE_F    (RPT * CH)             // 2416 elems
#define TILE_V4   (TILE_F / 4)           // 604 float4 (tile start 16B-aligned)
#define NWARP     22
#define THREADS   (NWARP * 32)           // 704
// two half arrays (q, t) of TILE_F per warp
#define SMEM_BYTES (NWARP * 2 * TILE_F * 2)   // 212,608 B dynamic

// Skeleton edges, premultiplied by 3 (channel offset of joint)
__constant__ int c_par3[N_EDGES] = {
    0,3,6,9,3,15,18,24,24,24,24,24,27,30,33,39,42,45,51,54,57,63,66,69,
    75,78,81,87,87,87,87,87,90,93,96,102,105,108,114,117,120,126,129,132,138,141,144};
__constant__ int c_chi3[N_EDGES] = {
    3,6,9,87,15,18,24,27,39,51,63,75,30,33,36,42,45,48,54,57,60,66,69,72,
    78,81,84,90,102,114,126,138,93,96,99,105,108,111,117,120,123,129,132,135,141,144,147};

// persistent accumulators; statically zero, last block resets after use
__device__ double   g_acc[2] = {0.0, 0.0};
__device__ unsigned g_ticket = 0;

// ---- edge-range math for one row (half-staged), edges [e0, e1) ----
__device__ __forceinline__ void do_edges_h(const __half* __restrict__ q,
                                           const __half* __restrict__ t,
                                           const int* __restrict__ s_a,
                                           const int* __restrict__ s_b,
                                           int e0, int e1, float& vel_acc)
{
    float vel = 0.f;
    #pragma unroll 4
    for (int e = e0; e < e1; e++) {
        int a = s_a[e];
        int b = s_b[e];

        float dp0 = __half2float(q[a])   - __half2float(q[b]);
        float dp1 = __half2float(q[a+1]) - __half2float(q[b+1]);
        float dp2 = __half2float(q[a+2]) - __half2float(q[b+2]);
        float dt0 = __half2float(t[a])   - __half2float(t[b]);
        float dt1 = __half2float(t[a+1]) - __half2float(t[b+1]);
        float dt2 = __half2float(t[a+2]) - __half2float(t[b+2]);

        float np = fmaf(dp0, dp0, fmaf(dp1, dp1, dp2 * dp2));
        float nt = fmaf(dt0, dt0, fmaf(dt1, dt1, dt2 * dt2));

        // ref: diff/(sqrt(n)+tiny); n==0 -> 0; n>0 -> rsqrt
        float ip = (np > 0.f) ? rsqrtf(np) : 0.f;
        float it = (nt > 0.f) ? rsqrtf(nt) : 0.f;

        float d0 = dp0 * ip - dt0 * it;
        float d1 = dp1 * ip - dt1 * it;
        float d2 = dp2 * ip - dt2 * it;

        // direction mask = raw channel mask at c*47+e (post-transpose layout)
        float m0 = __half2float(t[e]);
        float m1 = __half2float(t[47 + e]);
        float m2 = __half2float(t[94 + e]);

        vel += ((m0 != 0.f) ? d0 * d0 : 0.f)
             + ((m1 != 0.f) ? d1 * d1 : 0.f)
             + ((m2 != 0.f) ? d2 * d2 : 0.f);
    }
    vel_acc += vel;
}

// fp32 fallback for tail rows straight from gmem (unused for this shape)
__device__ __forceinline__ void process_row_gmem(const float* __restrict__ p,
                                                 const float* __restrict__ t,
                                                 const int* __restrict__ s_a,
                                                 const int* __restrict__ s_b,
                                                 float& l1_acc, float& vel_acc)
{
    float l1 = 0.f;
    float q[CH];
    #pragma unroll 8
    for (int i = 0; i < CH; i++) {
        float tv = t[i];
        float pv = p[i];
        float qv = (tv != 0.f) ? pv : 0.f;
        l1 += fabsf(qv - tv);
        q[i] = qv;
    }
    l1_acc += l1;

    float vel = 0.f;
    #pragma unroll 4
    for (int e = 0; e < N_EDGES; e++) {
        int a = s_a[e], b = s_b[e];
        float dp0 = q[a]-q[b], dp1 = q[a+1]-q[b+1], dp2 = q[a+2]-q[b+2];
        float dt0 = t[a]-t[b], dt1 = t[a+1]-t[b+1], dt2 = t[a+2]-t[b+2];
        float np = fmaf(dp0,dp0,fmaf(dp1,dp1,dp2*dp2));
        float nt = fmaf(dt0,dt0,fmaf(dt1,dt1,dt2*dt2));
        float ip = (np > 0.f) ? rsqrtf(np) : 0.f;
        float it = (nt > 0.f) ? rsqrtf(nt) : 0.f;
        float d0 = dp0*ip - dt0*it, d1 = dp1*ip - dt1*it, d2 = dp2*ip - dt2*it;
        vel += ((t[e]    != 0.f) ? d0*d0 : 0.f)
             + ((t[47+e] != 0.f) ? d1*d1 : 0.f)
             + ((t[94+e] != 0.f) ? d2*d2 : 0.f);
    }
    vel_acc += vel;
}

extern __shared__ __half smem_dyn[];

__device__ __forceinline__ uint32_t pack_half2(float lo, float hi) {
    __half2 h = __floats2half2_rn(lo, hi);
    return *reinterpret_cast<uint32_t*>(&h);
}

__global__ void __launch_bounds__(THREADS, 1)
reg_loss_kernel(const float* __restrict__ preds,
                const float* __restrict__ targets,
                float* __restrict__ out,
                int tiles, int rows)
{
    __shared__ int   s_a[N_EDGES], s_b[N_EDGES];
    __shared__ float s_red[2][NWARP];
    __shared__ bool  s_last;

    const int lane   = threadIdx.x & 31;
    const int wloc   = threadIdx.x >> 5;
    const int gwarp  = blockIdx.x * NWARP + wloc;
    const int nwarps = gridDim.x * NWARP;

    if (threadIdx.x < N_EDGES) {
        s_a[threadIdx.x] = c_par3[threadIdx.x];
        s_b[threadIdx.x] = c_chi3[threadIdx.x];
    }
    __syncthreads();

    // per-warp private half tiles: masked preds q + raw targets t
    // row stride 151 halfs (302 B) -> conflict-free/broadcast LDS pattern
    __half* sQ = smem_dyn + wloc * (2 * TILE_F);
    __half* sT = sQ + TILE_F;

    float l1_acc = 0.f, vel_acc = 0.f;

    for (int tile = gwarp; tile < tiles; tile += nwarps) {
        const float4* gp = (const float4*)(preds   + (size_t)tile * TILE_F);
        const float4* gt = (const float4*)(targets + (size_t)tile * TILE_F);
        uint2* dQ = (uint2*)sQ;    // 8B per float4-quad of halfs
        uint2* dT = (uint2*)sT;

        // ---- phase A: load fp32, fused L1 (exact fp32) + mask, stage fp16 ----
        #pragma unroll 5
        for (int i = lane; i < TILE_V4; i += 32) {
            float4 tv = gt[i];
            float4 pv = gp[i];

            float4 qv;
            qv.x = (tv.x != 0.f) ? pv.x : 0.f;
            qv.y = (tv.y != 0.f) ? pv.y : 0.f;
            qv.z = (tv.z != 0.f) ? pv.z : 0.f;
            qv.w = (tv.w != 0.f) ? pv.w : 0.f;

            // |q - t| == mask * |p - t| (t==0 -> q==0 -> 0) ; exact fp32
            l1_acc += fabsf(qv.x - tv.x) + fabsf(qv.y - tv.y)
                    + fabsf(qv.z - tv.z) + fabsf(qv.w - tv.w);

            dQ[i] = make_uint2(pack_half2(qv.x, qv.y), pack_half2(qv.z, qv.w));
            dT[i] = make_uint2(pack_half2(tv.x, tv.y), pack_half2(tv.z, tv.w));
        }
        __syncwarp();

        // ---- phase B: edges only; 2 lanes per row (24 + 23 edges) ----
        {
            int row  = lane >> 1;            // 0..15
            int half = lane & 1;
            int e0   = half ? 24 : 0;
            int e1   = half ? N_EDGES : 24;
            const __half* q = sQ + row * CH;
            const __half* t = sT + row * CH;
            do_edges_h(q, t, s_a, s_b, e0, e1, vel_acc);
        }
        __syncwarp();   // all lanes done before next tile overwrites
    }

    // tail rows (rows % RPT) straight from gmem (empty for this dataset)
    if (gwarp == 0) {
        for (int row = tiles * RPT + lane; row < rows; row += 32) {
            process_row_gmem(preds + (size_t)row * CH, targets + (size_t)row * CH,
                             s_a, s_b, l1_acc, vel_acc);
        }
    }

    // ---- warp reduce ----
    #pragma unroll
    for (int o = 16; o > 0; o >>= 1) {
        l1_acc  += __shfl_down_sync(0xFFFFFFFFu, l1_acc,  o);
        vel_acc += __shfl_down_sync(0xFFFFFFFFu, vel_acc, o);
    }
    if (lane == 0) { s_red[0][wloc] = l1_acc; s_red[1][wloc] = vel_acc; }
    __syncthreads();

    // ---- block reduce + global accumulate + last-block finalize ----
    if (threadIdx.x == 0) {
        float a = 0.f, v = 0.f;
        #pragma unroll
        for (int i = 0; i < NWARP; i++) { a += s_red[0][i]; v += s_red[1][i]; }
        atomicAdd(&g_acc[0], (double)a);
        atomicAdd(&g_acc[1], (double)v);
        __threadfence();
        unsigned tk = atomicAdd(&g_ticket, 1u);
        s_last = (tk == gridDim.x - 1);
    }
    __syncthreads();

    if (s_last && threadIdx.x == 0) {
        double l1  = g_acc[0] / ((double)rows * (double)CH);
        double vel = g_acc[1] / ((double)rows * (double)(N_EDGES * 3));
        out[0] = (float)(l1 + 0.1 * vel);
        // reset persistent state so every graph replay starts identically
        g_acc[0] = 0.0;
        g_acc[1] = 0.0;
        __threadfence();
        atomicExch(&g_ticket, 0u);
    }
}

extern "C" void kernel_launch(void* const* d_in, const int* in_sizes, int n_in,
                              void* d_out, int out_size)
{
    const float* preds   = (const float*)d_in[0];
    const float* targets = (const float*)d_in[1];
    float* out = (float*)d_out;

    int n     = in_sizes[0];
    int rows  = n / CH;            // B*T = 131072
    int tiles = rows / RPT;        // 8192

    cudaFuncSetAttribute(reg_loss_kernel,
                         cudaFuncAttributeMaxDynamicSharedMemorySize, SMEM_BYTES);

    // ONE launch: 148 blocks (1/SM, 212.6KB smem), 22 warps each
    reg_loss_kernel<<<148, THREADS, SMEM_BYTES>>>(preds, targets, out, tiles, rows);
}

// round 11
// speedup vs baseline: 1.0742x; 1.0742x over previous
#include <cuda_runtime.h>
#include <cstdint>

#define CH        151
#define N_EDGES   47
#define RPT       4                      // rows per warp-tile
#define TILE_F    (RPT * CH)             // 604 floats
#define TILE_V4   (TILE_F / 4)           // 151 float4 (tile start 16B-aligned)
#define NWARP     32
#define THREADS   (NWARP * 32)           // 1024
#define SMEM_BYTES (NWARP * 2 * TILE_F * 4)   // 154,624 B dynamic

// Skeleton edges, premultiplied by 3 (channel offset of joint)
__constant__ int c_par3[N_EDGES] = {
    0,3,6,9,3,15,18,24,24,24,24,24,27,30,33,39,42,45,51,54,57,63,66,69,
    75,78,81,87,87,87,87,87,90,93,96,102,105,108,114,117,120,126,129,132,138,141,144};
__constant__ int c_chi3[N_EDGES] = {
    3,6,9,87,15,18,24,27,39,51,63,75,30,33,36,42,45,48,54,57,60,66,69,72,
    78,81,84,90,102,114,126,138,93,96,99,105,108,111,117,120,123,129,132,135,141,144,147};

// persistent accumulators; statically zero, last block resets after use
__device__ double   g_acc[2] = {0.0, 0.0};
__device__ unsigned g_ticket = 0;

// ---- edge-range math for one row, edges [e0, e1) ----
// q = masked preds (q = (t!=0) ? p : 0), t = raw targets (== t*mask)
__device__ __forceinline__ void do_edges(const float* __restrict__ q,
                                         const float* __restrict__ t,
                                         const int* __restrict__ s_a,
                                         const int* __restrict__ s_b,
                                         int e0, int e1, float& vel_acc)
{
    float vel = 0.f;
    #pragma unroll 3
    for (int e = e0; e < e1; e++) {
        int a = s_a[e];
        int b = s_b[e];

        float dp0 = q[a]   - q[b];
        float dp1 = q[a+1] - q[b+1];
        float dp2 = q[a+2] - q[b+2];
        float dt0 = t[a]   - t[b];
        float dt1 = t[a+1] - t[b+1];
        float dt2 = t[a+2] - t[b+2];

        float np = fmaf(dp0, dp0, fmaf(dp1, dp1, dp2 * dp2));
        float nt = fmaf(dt0, dt0, fmaf(dt1, dt1, dt2 * dt2));

        // ref: diff/(sqrt(n)+tiny); n==0 -> 0; n>0 -> rsqrt
        float ip = (np > 0.f) ? rsqrtf(np) : 0.f;
        float it = (nt > 0.f) ? rsqrtf(nt) : 0.f;

        float d0 = dp0 * ip - dt0 * it;
        float d1 = dp1 * ip - dt1 * it;
        float d2 = dp2 * ip - dt2 * it;

        // direction mask = raw channel mask at c*47+e (post-transpose layout)
        float m0 = t[e];
        float m1 = t[47 + e];
        float m2 = t[94 + e];

        vel += ((m0 != 0.f) ? d0 * d0 : 0.f)
             + ((m1 != 0.f) ? d1 * d1 : 0.f)
             + ((m2 != 0.f) ? d2 * d2 : 0.f);
    }
    vel_acc += vel;
}

// fallback for tail rows straight from gmem (unused for this shape)
__device__ __forceinline__ void process_row_gmem(const float* __restrict__ p,
                                                 const float* __restrict__ t,
                                                 const int* __restrict__ s_a,
                                                 const int* __restrict__ s_b,
                                                 float& l1_acc, float& vel_acc)
{
    float l1 = 0.f;
    float q[CH];
    #pragma unroll 8
    for (int i = 0; i < CH; i++) {
        float tv = t[i];
        float pv = p[i];
        float qv = (tv != 0.f) ? pv : 0.f;
        l1 += fabsf(qv - tv);
        q[i] = qv;
    }
    l1_acc += l1;
    do_edges(q, t, s_a, s_b, 0, N_EDGES, vel_acc);
}

extern __shared__ float smem_dyn[];

__global__ void __launch_bounds__(THREADS, 1)
reg_loss_kernel(const float* __restrict__ preds,
                const float* __restrict__ targets,
                float* __restrict__ out,
                int tiles, int rows)
{
    __shared__ int   s_a[N_EDGES], s_b[N_EDGES];
    __shared__ float s_red[2][NWARP];
    __shared__ bool  s_last;

    const int lane   = threadIdx.x & 31;
    const int wloc   = threadIdx.x >> 5;
    const int gwarp  = blockIdx.x * NWARP + wloc;
    const int nwarps = gridDim.x * NWARP;

    if (threadIdx.x < N_EDGES) {
        s_a[threadIdx.x] = c_par3[threadIdx.x];
        s_b[threadIdx.x] = c_chi3[threadIdx.x];
    }
    __syncthreads();

    // per-warp private tile: masked preds q + raw targets t
    // row stride 151 (odd) -> rows land on shifted bank phases
    float* sQ = smem_dyn + wloc * (2 * TILE_F);
    float* sT = sQ + TILE_F;

    float l1_acc = 0.f, vel_acc = 0.f;

    for (int tile = gwarp; tile < tiles; tile += nwarps) {
        const float4* gp = (const float4*)(preds   + (size_t)tile * TILE_F);
        const float4* gt = (const float4*)(targets + (size_t)tile * TILE_F);
        float4* dQ = (float4*)sQ;
        float4* dT = (float4*)sT;

        // ---- phase A: coalesced load + fused L1 (exact fp32) + mask + stage ----
        #pragma unroll 5
        for (int i = lane; i < TILE_V4; i += 32) {
            float4 tv = gt[i];
            float4 pv = gp[i];

            float4 qv;
            qv.x = (tv.x != 0.f) ? pv.x : 0.f;
            qv.y = (tv.y != 0.f) ? pv.y : 0.f;
            qv.z = (tv.z != 0.f) ? pv.z : 0.f;
            qv.w = (tv.w != 0.f) ? pv.w : 0.f;

            // |q - t| == mask * |p - t| (t==0 -> q==0 -> 0)
            l1_acc += fabsf(qv.x - tv.x) + fabsf(qv.y - tv.y)
                    + fabsf(qv.z - tv.z) + fabsf(qv.w - tv.w);

            dQ[i] = qv;
            dT[i] = tv;
        }
        __syncwarp();

        // ---- phase B: edges only; 8 lanes per row (6*7 + 5 edges) ----
        {
            int row = lane >> 3;             // 0..3
            int oct = lane & 7;              // 0..7
            int e0  = oct * 6;
            int e1  = (oct == 7) ? N_EDGES : e0 + 6;
            const float* q = sQ + row * CH;
            const float* t = sT + row * CH;
            do_edges(q, t, s_a, s_b, e0, e1, vel_acc);
        }
        __syncwarp();   // all lanes done before next tile overwrites
    }

    // tail rows (rows % RPT) straight from gmem (empty for this dataset)
    if (gwarp == 0) {
        for (int row = tiles * RPT + lane; row < rows; row += 32) {
            process_row_gmem(preds + (size_t)row * CH, targets + (size_t)row * CH,
                             s_a, s_b, l1_acc, vel_acc);
        }
    }

    // ---- warp reduce ----
    #pragma unroll
    for (int o = 16; o > 0; o >>= 1) {
        l1_acc  += __shfl_down_sync(0xFFFFFFFFu, l1_acc,  o);
        vel_acc += __shfl_down_sync(0xFFFFFFFFu, vel_acc, o);
    }
    if (lane == 0) { s_red[0][wloc] = l1_acc; s_red[1][wloc] = vel_acc; }
    __syncthreads();

    // ---- block reduce + global accumulate + last-block finalize ----
    if (threadIdx.x == 0) {
        float a = 0.f, v = 0.f;
        #pragma unroll
        for (int i = 0; i < NWARP; i++) { a += s_red[0][i]; v += s_red[1][i]; }
        atomicAdd(&g_acc[0], (double)a);
        atomicAdd(&g_acc[1], (double)v);
        __threadfence();
        unsigned tk = atomicAdd(&g_ticket, 1u);
        s_last = (tk == gridDim.x - 1);
    }
    __syncthreads();

    if (s_last && threadIdx.x == 0) {
        double l1  = g_acc[0] / ((double)rows * (double)CH);
        double vel = g_acc[1] / ((double)rows * (double)(N_EDGES * 3));
        out[0] = (float)(l1 + 0.1 * vel);
        // reset persistent state so every graph replay starts identically
        g_acc[0] = 0.0;
        g_acc[1] = 0.0;
        __threadfence();
        atomicExch(&g_ticket, 0u);
    }
}

extern "C" void kernel_launch(void* const* d_in, const int* in_sizes, int n_in,
                              void* d_out, int out_size)
{
    const float* preds   = (const float*)d_in[0];
    const float* targets = (const float*)d_in[1];
    float* out = (float*)d_out;

    int n     = in_sizes[0];
    int rows  = n / CH;            // B*T = 131072
    int tiles = rows / RPT;        // 32768

    cudaFuncSetAttribute(reg_loss_kernel,
                         cudaFuncAttributeMaxDynamicSharedMemorySize, SMEM_BYTES);

    // ONE launch: 148 blocks (1/SM, 154.6KB smem), 32 warps each -> occ 50%
    reg_loss_kernel<<<148, THREADS, SMEM_BYTES>>>(preds, targets, out, tiles, rows);
}

// round 12
// speedup vs baseline: 1.7284x; 1.6090x over previous
#include <cuda_runtime.h>
#include <cstdint>

#define CH          151
#define N_EDGES     47
#define GROUP_ROWS  32                    // rows per block-group == lanes
#define GROUP_F     (GROUP_ROWS * CH)     // 4832 floats per array
#define GROUP_V4    (GROUP_F / 4)         // 1208 float4 (16B-aligned: 4832%4==0)
#define NWARP       16
#define THREADS     (NWARP * 32)          // 512
// double buffer x (p, t)
#define SMEM_BYTES  (2 * 2 * GROUP_F * 4) // 77,312 B dynamic

// Skeleton edges, premultiplied by 3 (channel offset of joint)
__constant__ int c_par3[N_EDGES] = {
    0,3,6,9,3,15,18,24,24,24,24,24,27,30,33,39,42,45,51,54,57,63,66,69,
    75,78,81,87,87,87,87,87,90,93,96,102,105,108,114,117,120,126,129,132,138,141,144};
__constant__ int c_chi3[N_EDGES] = {
    3,6,9,87,15,18,24,27,39,51,63,75,30,33,36,42,45,48,54,57,60,66,69,72,
    78,81,84,90,102,114,126,138,93,96,99,105,108,111,117,120,123,129,132,135,141,144,147};

// persistent accumulators; statically zero, last block resets after use
__device__ double   g_acc[2] = {0.0, 0.0};
__device__ unsigned g_ticket = 0;

__device__ __forceinline__ void cp16(void* s, const void* g) {
    uint32_t sa = (uint32_t)__cvta_generic_to_shared(s);
    asm volatile("cp.async.cg.shared.global [%0], [%1], 16;" :: "r"(sa), "l"(g));
}

extern __shared__ float smem_dyn[];

// stage group g's raw p and t into buffer buf (all threads cooperate)
__device__ __forceinline__ void stage_group(const float* __restrict__ preds,
                                            const float* __restrict__ targets,
                                            long g, int buf)
{
    const float4* gp = (const float4*)(preds   + (size_t)g * GROUP_F);
    const float4* gt = (const float4*)(targets + (size_t)g * GROUP_F);
    float4* dP = (float4*)(smem_dyn + (size_t)buf * (2 * GROUP_F));
    float4* dT = dP + GROUP_V4;
    #pragma unroll 2
    for (int i = threadIdx.x; i < GROUP_V4; i += THREADS) {
        cp16(dP + i, gp + i);
        cp16(dT + i, gt + i);
    }
}

// tail fallback straight from gmem (unused for this shape, kept for generality)
__device__ __forceinline__ void process_row_gmem(const float* __restrict__ p,
                                                 const float* __restrict__ t,
                                                 float& l1_acc, float& vel_acc)
{
    float l1 = 0.f;
    float q[CH];
    #pragma unroll 8
    for (int i = 0; i < CH; i++) {
        float tv = t[i];
        float pv = p[i];
        float qv = (tv != 0.f) ? pv : 0.f;
        l1 += fabsf(qv - tv);
        q[i] = qv;
    }
    l1_acc += l1;

    float vel = 0.f;
    for (int e = 0; e < N_EDGES; e++) {
        int a = c_par3[e], b = c_chi3[e];
        float dp0 = q[a]-q[b], dp1 = q[a+1]-q[b+1], dp2 = q[a+2]-q[b+2];
        float dt0 = t[a]-t[b], dt1 = t[a+1]-t[b+1], dt2 = t[a+2]-t[b+2];
        float np = fmaf(dp0,dp0,fmaf(dp1,dp1,dp2*dp2));
        float nt = fmaf(dt0,dt0,fmaf(dt1,dt1,dt2*dt2));
        float ip = (np > 0.f) ? rsqrtf(np) : 0.f;
        float it = (nt > 0.f) ? rsqrtf(nt) : 0.f;
        float d0 = dp0*ip - dt0*it, d1 = dp1*ip - dt1*it, d2 = dp2*ip - dt2*it;
        vel += ((t[e]    != 0.f) ? d0*d0 : 0.f)
             + ((t[47+e] != 0.f) ? d1*d1 : 0.f)
             + ((t[94+e] != 0.f) ? d2*d2 : 0.f);
    }
    vel_acc += vel;
}

__global__ void __launch_bounds__(THREADS, 2)
reg_loss_kernel(const float* __restrict__ preds,
                const float* __restrict__ targets,
                float* __restrict__ out,
                int groups, int rows)
{
    __shared__ int   s_a[N_EDGES], s_b[N_EDGES];
    __shared__ float s_red[2][NWARP];
    __shared__ bool  s_last;

    const int lane = threadIdx.x & 31;
    const int wloc = threadIdx.x >> 5;

    if (threadIdx.x < N_EDGES) {
        s_a[threadIdx.x] = c_par3[threadIdx.x];
        s_b[threadIdx.x] = c_chi3[threadIdx.x];
    }
    __syncthreads();

    // number of groups this block owns (grid-stride over groups)
    const int kcnt = (blockIdx.x < (unsigned)groups)
                   ? ((groups - 1 - blockIdx.x) / gridDim.x + 1) : 0;

    float l1_acc = 0.f, vel_acc = 0.f;

    if (kcnt > 0) {
        stage_group(preds, targets, blockIdx.x, 0);
        asm volatile("cp.async.commit_group;");
    }

    for (int k = 0; k < kcnt; k++) {
        if (k + 1 < kcnt) {
            stage_group(preds, targets,
                        blockIdx.x + (long)(k + 1) * gridDim.x, (k + 1) & 1);
            asm volatile("cp.async.commit_group;");
            asm volatile("cp.async.wait_group 1;" ::: "memory");
        } else {
            asm volatile("cp.async.wait_group 0;" ::: "memory");
        }
        __syncthreads();   // whole buffer visible to all threads

        const float* sP = smem_dyn + (size_t)(k & 1) * (2 * GROUP_F);
        const float* sT = sP + GROUP_F;
        // lane owns row == lane; stride 151 words (odd) -> every access below
        // has bank = (23*lane + const) % 32 : a permutation -> 1 wavefront/LDS
        const float* prow = sP + lane * CH;
        const float* trow = sT + lane * CH;

        // ---- pass 1: L1 term; channels split across warps ----
        #pragma unroll 5
        for (int c = wloc; c < CH; c += NWARP) {
            float tv = trow[c];
            float pv = prow[c];
            l1_acc += (tv != 0.f) ? fabsf(pv - tv) : 0.f;
        }

        // ---- pass 2: edges; edges split across warps, lane = row ----
        #pragma unroll 3
        for (int e = wloc; e < N_EDGES; e += NWARP) {
            int a = s_a[e];
            int b = s_b[e];

            float ta0 = trow[a],   ta1 = trow[a+1], ta2 = trow[a+2];
            float tb0 = trow[b],   tb1 = trow[b+1], tb2 = trow[b+2];
            float pa0 = prow[a],   pa1 = prow[a+1], pa2 = prow[a+2];
            float pb0 = prow[b],   pb1 = prow[b+1], pb2 = prow[b+2];

            // masked preds (mask from targets)
            float qa0 = (ta0 != 0.f) ? pa0 : 0.f;
            float qa1 = (ta1 != 0.f) ? pa1 : 0.f;
            float qa2 = (ta2 != 0.f) ? pa2 : 0.f;
            float qb0 = (tb0 != 0.f) ? pb0 : 0.f;
            float qb1 = (tb1 != 0.f) ? pb1 : 0.f;
            float qb2 = (tb2 != 0.f) ? pb2 : 0.f;

            float dp0 = qa0 - qb0, dp1 = qa1 - qb1, dp2 = qa2 - qb2;
            float dt0 = ta0 - tb0, dt1 = ta1 - tb1, dt2 = ta2 - tb2;

            float np = fmaf(dp0, dp0, fmaf(dp1, dp1, dp2 * dp2));
            float nt = fmaf(dt0, dt0, fmaf(dt1, dt1, dt2 * dt2));

            // ref: diff/(sqrt(n)+tiny); n==0 -> 0; n>0 -> rsqrt
            float ip = (np > 0.f) ? rsqrtf(np) : 0.f;
            float it = (nt > 0.f) ? rsqrtf(nt) : 0.f;

            float d0 = dp0 * ip - dt0 * it;
            float d1 = dp1 * ip - dt1 * it;
            float d2 = dp2 * ip - dt2 * it;

            // direction mask = raw channel mask at c*47+e (post-transpose layout)
            float m0 = trow[e];
            float m1 = trow[47 + e];
            float m2 = trow[94 + e];

            vel_acc += ((m0 != 0.f) ? d0 * d0 : 0.f)
                     + ((m1 != 0.f) ? d1 * d1 : 0.f)
                     + ((m2 != 0.f) ? d2 * d2 : 0.f);
        }
        __syncthreads();   // all reads done before next stage overwrites
    }

    // tail rows (rows % 32) straight from gmem (empty for this dataset)
    if (blockIdx.x == 0 && wloc == 0) {
        for (int row = groups * GROUP_ROWS + lane; row < rows; row += 32) {
            process_row_gmem(preds + (size_t)row * CH,
                             targets + (size_t)row * CH, l1_acc, vel_acc);
        }
    }

    // ---- warp reduce ----
    #pragma unroll
    for (int o = 16; o > 0; o >>= 1) {
        l1_acc  += __shfl_down_sync(0xFFFFFFFFu, l1_acc,  o);
        vel_acc += __shfl_down_sync(0xFFFFFFFFu, vel_acc, o);
    }
    if (lane == 0) { s_red[0][wloc] = l1_acc; s_red[1][wloc] = vel_acc; }
    __syncthreads();

    // ---- block reduce + global accumulate + last-block finalize ----
    if (threadIdx.x == 0) {
        float a = 0.f, v = 0.f;
        #pragma unroll
        for (int i = 0; i < NWARP; i++) { a += s_red[0][i]; v += s_red[1][i]; }
        atomicAdd(&g_acc[0], (double)a);
        atomicAdd(&g_acc[1], (double)v);
        __threadfence();
        unsigned tk = atomicAdd(&g_ticket, 1u);
        s_last = (tk == gridDim.x - 1);
    }
    __syncthreads();

    if (s_last && threadIdx.x == 0) {
        double l1  = g_acc[0] / ((double)rows * (double)CH);
        double vel = g_acc[1] / ((double)rows * (double)(N_EDGES * 3));
        out[0] = (float)(l1 + 0.1 * vel);
        // reset persistent state so every graph replay starts identically
        g_acc[0] = 0.0;
        g_acc[1] = 0.0;
        __threadfence();
        atomicExch(&g_ticket, 0u);
    }
}

extern "C" void kernel_launch(void* const* d_in, const int* in_sizes, int n_in,
                              void* d_out, int out_size)
{
    const float* preds   = (const float*)d_in[0];
    const float* targets = (const float*)d_in[1];
    float* out = (float*)d_out;

    int n      = in_sizes[0];
    int rows   = n / CH;               // B*T = 131072
    int groups = rows / GROUP_ROWS;    // 4096

    cudaFuncSetAttribute(reg_loss_kernel,
                         cudaFuncAttributeMaxDynamicSharedMemorySize, SMEM_BYTES);

    // ONE launch: 296 blocks (2/SM, 77.3KB smem each), 16 warps per block
    reg_loss_kernel<<<296, THREADS, SMEM_BYTES>>>(preds, targets, out,
                                                  groups, rows);
}

// round 13
// speedup vs baseline: 1.8467x; 1.0685x over previous
#include <cuda_runtime.h>
#include <cfloat>
#include <cstdint>

#define CH          151
#define N_EDGES     47
#define GROUP_ROWS  32                    // rows per block-group == lanes
#define GROUP_F     (GROUP_ROWS * CH)     // 4832 floats per array
#define GROUP_V4    (GROUP_F / 4)         // 1208 float4
#define NWARP       16
#define THREADS     (NWARP * 32)          // 512
#define NV_ITERS    3                     // ceil(1208/512)
// double buffer x (q, t)
#define SMEM_BYTES  (2 * 2 * GROUP_F * 4) // 77,312 B dynamic

// Skeleton edges, premultiplied by 3 (channel offset of joint)
__constant__ int c_par3[N_EDGES] = {
    0,3,6,9,3,15,18,24,24,24,24,24,27,30,33,39,42,45,51,54,57,63,66,69,
    75,78,81,87,87,87,87,87,90,93,96,102,105,108,114,117,120,126,129,132,138,141,144};
__constant__ int c_chi3[N_EDGES] = {
    3,6,9,87,15,18,24,27,39,51,63,75,30,33,36,42,45,48,54,57,60,66,69,72,
    78,81,84,90,102,114,126,138,93,96,99,105,108,111,117,120,123,129,132,135,141,144,147};

// persistent accumulators; statically zero, last block resets after use
__device__ double   g_acc[2] = {0.0, 0.0};
__device__ unsigned g_ticket = 0;

extern __shared__ float smem_dyn[];

// tail fallback straight from gmem (unused for this shape, kept for generality)
__device__ __forceinline__ void process_row_gmem(const float* __restrict__ p,
                                                 const float* __restrict__ t,
                                                 float& l1_acc, float& vel_acc)
{
    float l1 = 0.f;
    float q[CH];
    #pragma unroll 8
    for (int i = 0; i < CH; i++) {
        float tv = t[i];
        float pv = p[i];
        float qv = (tv != 0.f) ? pv : 0.f;
        l1 += fabsf(qv - tv);
        q[i] = qv;
    }
    l1_acc += l1;

    float vel = 0.f;
    for (int e = 0; e < N_EDGES; e++) {
        int a = c_par3[e], b = c_chi3[e];
        float dp0 = q[a]-q[b], dp1 = q[a+1]-q[b+1], dp2 = q[a+2]-q[b+2];
        float dt0 = t[a]-t[b], dt1 = t[a+1]-t[b+1], dt2 = t[a+2]-t[b+2];
        float np = fmaf(dp0,dp0,fmaf(dp1,dp1,dp2*dp2));
        float nt = fmaf(dt0,dt0,fmaf(dt1,dt1,dt2*dt2));
        float ip = rsqrtf(fmaxf(np, FLT_MIN));
        float it = rsqrtf(fmaxf(nt, FLT_MIN));
        float d0 = dp0*ip - dt0*it, d1 = dp1*ip - dt1*it, d2 = dp2*ip - dt2*it;
        if (t[e]      != 0.f) vel = fmaf(d0, d0, vel);
        if (t[47 + e] != 0.f) vel = fmaf(d1, d1, vel);
        if (t[94 + e] != 0.f) vel = fmaf(d2, d2, vel);
    }
    vel_acc += vel;
}

__global__ void __launch_bounds__(THREADS, 2)
reg_loss_kernel(const float* __restrict__ preds,
                const float* __restrict__ targets,
                float* __restrict__ out,
                int groups, int rows)
{
    __shared__ int   s_a[N_EDGES], s_b[N_EDGES];
    __shared__ float s_red[2][NWARP];
    __shared__ bool  s_last;

    const int lane = threadIdx.x & 31;
    const int wloc = threadIdx.x >> 5;
    const int tid  = threadIdx.x;

    if (tid < N_EDGES) {
        s_a[tid] = c_par3[tid];
        s_b[tid] = c_chi3[tid];
    }
    __syncthreads();

    const int kcnt = (blockIdx.x < (unsigned)groups)
                   ? ((groups - 1 - blockIdx.x) / gridDim.x + 1) : 0;

    float l1_acc = 0.f, vel_acc = 0.f;

    // register prefetch buffers for one group (this thread's slice)
    float4 pbuf[NV_ITERS], tbuf[NV_ITERS];

    // load group g's slice into registers
    auto load_group = [&](long g) {
        const float4* gp = (const float4*)(preds   + (size_t)g * GROUP_F);
        const float4* gt = (const float4*)(targets + (size_t)g * GROUP_F);
        #pragma unroll
        for (int i = 0; i < NV_ITERS; i++) {
            int idx = tid + i * THREADS;
            if (idx < GROUP_V4) {
                pbuf[i] = gp[idx];
                tbuf[i] = gt[idx];
            }
        }
    };

    if (kcnt > 0) load_group(blockIdx.x);

    for (int k = 0; k < kcnt; k++) {
        float* sQ = smem_dyn + (size_t)(k & 1) * (2 * GROUP_F);
        float* sT = sQ + GROUP_F;

        // ---- stage: fused L1 (exact fp32) + mask, STS q (masked p) + raw t ----
        #pragma unroll
        for (int i = 0; i < NV_ITERS; i++) {
            int idx = tid + i * THREADS;
            if (idx < GROUP_V4) {
                float4 tv = tbuf[i];
                float4 pv = pbuf[i];
                float4 qv;
                qv.x = (tv.x != 0.f) ? pv.x : 0.f;
                qv.y = (tv.y != 0.f) ? pv.y : 0.f;
                qv.z = (tv.z != 0.f) ? pv.z : 0.f;
                qv.w = (tv.w != 0.f) ? pv.w : 0.f;
                // |q - t| == mask * |p - t| (t==0 -> q==0 -> 0)
                l1_acc += fabsf(qv.x - tv.x) + fabsf(qv.y - tv.y)
                        + fabsf(qv.z - tv.z) + fabsf(qv.w - tv.w);
                ((float4*)sQ)[idx] = qv;
                ((float4*)sT)[idx] = tv;
            }
        }

        // issue next group's LDGs early; they complete under pass 2
        if (k + 1 < kcnt)
            load_group(blockIdx.x + (long)(k + 1) * gridDim.x);

        __syncthreads();   // staged buffer visible to all threads

        // ---- pass 2: edges; lane = row (stride 151 words -> conflict-free) ----
        {
            const float* qrow = sQ + lane * CH;
            const float* trow = sT + lane * CH;

            #pragma unroll 3
            for (int e = wloc; e < N_EDGES; e += NWARP) {
                int a = s_a[e];
                int b = s_b[e];

                float dp0 = qrow[a]   - qrow[b];
                float dp1 = qrow[a+1] - qrow[b+1];
                float dp2 = qrow[a+2] - qrow[b+2];
                float dt0 = trow[a]   - trow[b];
                float dt1 = trow[a+1] - trow[b+1];
                float dt2 = trow[a+2] - trow[b+2];

                float np = fmaf(dp0, dp0, fmaf(dp1, dp1, dp2 * dp2));
                float nt = fmaf(dt0, dt0, fmaf(dt1, dt1, dt2 * dt2));

                // n==0 -> dp==0 -> d==0 regardless of clamp; exact vs ref
                float ip = rsqrtf(fmaxf(np, FLT_MIN));
                float it = rsqrtf(fmaxf(nt, FLT_MIN));

                float d0 = dp0 * ip - dt0 * it;
                float d1 = dp1 * ip - dt1 * it;
                float d2 = dp2 * ip - dt2 * it;

                // direction mask = raw channel mask at c*47+e (post-transpose)
                float m0 = trow[e];
                float m1 = trow[47 + e];
                float m2 = trow[94 + e];

                if (m0 != 0.f) vel_acc = fmaf(d0, d0, vel_acc);
                if (m1 != 0.f) vel_acc = fmaf(d1, d1, vel_acc);
                if (m2 != 0.f) vel_acc = fmaf(d2, d2, vel_acc);
            }
        }
        __syncthreads();   // all reads done before next stage overwrites
    }

    // tail rows (rows % 32) straight from gmem (empty for this dataset)
    if (blockIdx.x == 0 && wloc == 0) {
        for (int row = groups * GROUP_ROWS + lane; row < rows; row += 32) {
            process_row_gmem(preds + (size_t)row * CH,
                             targets + (size_t)row * CH, l1_acc, vel_acc);
        }
    }

    // ---- warp reduce ----
    #pragma unroll
    for (int o = 16; o > 0; o >>= 1) {
        l1_acc  += __shfl_down_sync(0xFFFFFFFFu, l1_acc,  o);
        vel_acc += __shfl_down_sync(0xFFFFFFFFu, vel_acc, o);
    }
    if (lane == 0) { s_red[0][wloc] = l1_acc; s_red[1][wloc] = vel_acc; }
    __syncthreads();

    // ---- block reduce + global accumulate + last-block finalize ----
    if (threadIdx.x == 0) {
        float a = 0.f, v = 0.f;
        #pragma unroll
        for (int i = 0; i < NWARP; i++) { a += s_red[0][i]; v += s_red[1][i]; }
        atomicAdd(&g_acc[0], (double)a);
        atomicAdd(&g_acc[1], (double)v);
        __threadfence();
        unsigned tk = atomicAdd(&g_ticket, 1u);
        s_last = (tk == gridDim.x - 1);
    }
    __syncthreads();

    if (s_last && threadIdx.x == 0) {
        double l1  = g_acc[0] / ((double)rows * (double)CH);
        double vel = g_acc[1] / ((double)rows * (double)(N_EDGES * 3));
        out[0] = (float)(l1 + 0.1 * vel);
        // reset persistent state so every graph replay starts identically
        g_acc[0] = 0.0;
        g_acc[1] = 0.0;
        __threadfence();
        atomicExch(&g_ticket, 0u);
    }
}

extern "C" void kernel_launch(void* const* d_in, const int* in_sizes, int n_in,
                              void* d_out, int out_size)
{
    const float* preds   = (const float*)d_in[0];
    const float* targets = (const float*)d_in[1];
    float* out = (float*)d_out;

    int n      = in_sizes[0];
    int rows   = n / CH;               // B*T = 131072
    int groups = rows / GROUP_ROWS;    // 4096

    cudaFuncSetAttribute(reg_loss_kernel,
                         cudaFuncAttributeMaxDynamicSharedMemorySize, SMEM_BYTES);

    // ONE launch: 296 blocks (2/SM, 77.3KB smem each), 16 warps per block
    reg_loss_kernel<<<296, THREADS, SMEM_BYTES>>>(preds, targets, out,
                                                  groups, rows);
}

// round 14
// speedup vs baseline: 2.0484x; 1.1092x over previous
#include <cuda_runtime.h>
#include <cfloat>
#include <cstdint>

#define CH          151
#define N_EDGES     47
#define GROUP_ROWS  32                    // rows per block-group == lanes
#define GROUP_F     (GROUP_ROWS * CH)     // 4832 floats per array
#define GROUP_V4    (GROUP_F / 4)         // 1208 float4
#define NWARP       16
#define THREADS     (NWARP * 32)          // 512
#define NV_ITERS    3                     // ceil(1208/512)
// double buffer x (q, t)
#define SMEM_BYTES  (2 * 2 * GROUP_F * 4) // 77,312 B dynamic

// Skeleton edges, premultiplied by 3 (channel offset of joint)
__constant__ int c_par3[N_EDGES] = {
    0,3,6,9,3,15,18,24,24,24,24,24,27,30,33,39,42,45,51,54,57,63,66,69,
    75,78,81,87,87,87,87,87,90,93,96,102,105,108,114,117,120,126,129,132,138,141,144};
__constant__ int c_chi3[N_EDGES] = {
    3,6,9,87,15,18,24,27,39,51,63,75,30,33,36,42,45,48,54,57,60,66,69,72,
    78,81,84,90,102,114,126,138,93,96,99,105,108,111,117,120,123,129,132,135,141,144,147};

// persistent accumulators; statically zero, last block resets after use
__device__ double   g_acc[2] = {0.0, 0.0};
__device__ unsigned g_ticket = 0;

extern __shared__ float smem_dyn[];

// tail fallback straight from gmem (unused for this shape, kept for generality)
__device__ __forceinline__ void process_row_gmem(const float* __restrict__ p,
                                                 const float* __restrict__ t,
                                                 float& l1_acc, float& vel_acc)
{
    float l1 = 0.f;
    float q[CH];
    #pragma unroll 8
    for (int i = 0; i < CH; i++) {
        float tv = t[i];
        float pv = p[i];
        float qv = (tv != 0.f) ? pv : 0.f;
        l1 += (tv != 0.f) ? fabsf(pv - tv) : 0.f;
        q[i] = qv;
    }
    l1_acc += l1;

    float vel = 0.f;
    for (int e = 0; e < N_EDGES; e++) {
        int a = c_par3[e], b = c_chi3[e];
        float dp0 = q[a]-q[b], dp1 = q[a+1]-q[b+1], dp2 = q[a+2]-q[b+2];
        float dt0 = t[a]-t[b], dt1 = t[a+1]-t[b+1], dt2 = t[a+2]-t[b+2];
        float np = fmaf(dp0,dp0,fmaf(dp1,dp1,dp2*dp2));
        float nt = fmaf(dt0,dt0,fmaf(dt1,dt1,dt2*dt2));
        float ip = rsqrtf(fmaxf(np, FLT_MIN));
        float it = rsqrtf(fmaxf(nt, FLT_MIN));
        float d0 = dp0*ip - dt0*it, d1 = dp1*ip - dt1*it, d2 = dp2*ip - dt2*it;
        if (t[e]      != 0.f) vel = fmaf(d0, d0, vel);
        if (t[47 + e] != 0.f) vel = fmaf(d1, d1, vel);
        if (t[94 + e] != 0.f) vel = fmaf(d2, d2, vel);
    }
    vel_acc += vel;
}

__global__ void __launch_bounds__(THREADS, 2)
reg_loss_kernel(const float* __restrict__ preds,
                const float* __restrict__ targets,
                float* __restrict__ out,
                int groups, int rows)
{
    __shared__ int   s_a[N_EDGES], s_b[N_EDGES];
    __shared__ float s_red[2][NWARP];
    __shared__ bool  s_last;

    const int lane = threadIdx.x & 31;
    const int wloc = threadIdx.x >> 5;
    const int tid  = threadIdx.x;

    if (tid < N_EDGES) {
        s_a[tid] = c_par3[tid];
        s_b[tid] = c_chi3[tid];
    }
    __syncthreads();

    const int kcnt = (blockIdx.x < (unsigned)groups)
                   ? ((groups - 1 - blockIdx.x) / gridDim.x + 1) : 0;

    float l1_acc = 0.f, vel_acc = 0.f;

    // register prefetch buffers for one group (this thread's slice)
    float4 pbuf[NV_ITERS], tbuf[NV_ITERS];

    auto load_group = [&](long g) {
        const float4* gp = (const float4*)(preds   + (size_t)g * GROUP_F);
        const float4* gt = (const float4*)(targets + (size_t)g * GROUP_F);
        #pragma unroll
        for (int i = 0; i < NV_ITERS; i++) {
            int idx = tid + i * THREADS;
            if (idx < GROUP_V4) {
                pbuf[i] = gp[idx];
                tbuf[i] = gt[idx];
            }
        }
    };

    if (kcnt > 0) load_group(blockIdx.x);

    for (int k = 0; k < kcnt; k++) {
        float* sQ = smem_dyn + (size_t)(k & 1) * (2 * GROUP_F);
        float* sT = sQ + GROUP_F;

        // ---- stage: fused L1 (exact fp32) + mask, STS q (masked p) + raw t ----
        // Writes buffer k&1; laggard warps may still be reading buffer (k-1)&1
        // in their pass 2 — disjoint regions, no race (double buffer).
        #pragma unroll
        for (int i = 0; i < NV_ITERS; i++) {
            int idx = tid + i * THREADS;
            if (idx < GROUP_V4) {
                float4 tv = tbuf[i];
                float4 pv = pbuf[i];
                float4 qv;
                qv.x = (tv.x != 0.f) ? pv.x : 0.f;
                qv.y = (tv.y != 0.f) ? pv.y : 0.f;
                qv.z = (tv.z != 0.f) ? pv.z : 0.f;
                qv.w = (tv.w != 0.f) ? pv.w : 0.f;
                l1_acc += ((tv.x != 0.f) ? fabsf(pv.x - tv.x) : 0.f)
                        + ((tv.y != 0.f) ? fabsf(pv.y - tv.y) : 0.f)
                        + ((tv.z != 0.f) ? fabsf(pv.z - tv.z) : 0.f)
                        + ((tv.w != 0.f) ? fabsf(pv.w - tv.w) : 0.f);
                ((float4*)sQ)[idx] = qv;
                ((float4*)sT)[idx] = tv;
            }
        }

        // issue next group's LDGs now; they complete under pass 2
        if (k + 1 < kcnt)
            load_group(blockIdx.x + (long)(k + 1) * gridDim.x);

        // ONE sync per group: all warps finished staging buffer k&1.
        // Reaching here also implies every warp finished pass2(k-1), so the
        // upcoming stage(k+1) -> buffer (k+1)&1 and stage(k+2) -> buffer k&1
        // (only after the NEXT sync) can never race a reader.
        __syncthreads();

        // ---- pass 2: edges; lane = row (stride 151 words -> conflict-free) ----
        {
            const float* qrow = sQ + lane * CH;
            const float* trow = sT + lane * CH;

            #pragma unroll
            for (int e = wloc; e < N_EDGES; e += NWARP) {
                int a = s_a[e];
                int b = s_b[e];

                float dp0 = qrow[a]   - qrow[b];
                float dp1 = qrow[a+1] - qrow[b+1];
                float dp2 = qrow[a+2] - qrow[b+2];
                float dt0 = trow[a]   - trow[b];
                float dt1 = trow[a+1] - trow[b+1];
                float dt2 = trow[a+2] - trow[b+2];

                float np = fmaf(dp0, dp0, fmaf(dp1, dp1, dp2 * dp2));
                float nt = fmaf(dt0, dt0, fmaf(dt1, dt1, dt2 * dt2));

                // n==0 -> dp==0 -> d==0 regardless of clamp; exact vs ref
                float ip = rsqrtf(fmaxf(np, FLT_MIN));
                float it = rsqrtf(fmaxf(nt, FLT_MIN));

                float d0 = dp0 * ip - dt0 * it;
                float d1 = dp1 * ip - dt1 * it;
                float d2 = dp2 * ip - dt2 * it;

                // direction mask = raw channel mask at c*47+e (post-transpose)
                float m0 = trow[e];
                float m1 = trow[47 + e];
                float m2 = trow[94 + e];

                if (m0 != 0.f) vel_acc = fmaf(d0, d0, vel_acc);
                if (m1 != 0.f) vel_acc = fmaf(d1, d1, vel_acc);
                if (m2 != 0.f) vel_acc = fmaf(d2, d2, vel_acc);
            }
        }
        // NO trailing sync: next iteration's stage writes the other buffer.
    }

    // tail rows (rows % 32) straight from gmem (empty for this dataset)
    if (blockIdx.x == 0 && wloc == 0) {
        for (int row = groups * GROUP_ROWS + lane; row < rows; row += 32) {
            process_row_gmem(preds + (size_t)row * CH,
                             targets + (size_t)row * CH, l1_acc, vel_acc);
        }
    }

    // ---- warp reduce ----
    #pragma unroll
    for (int o = 16; o > 0; o >>= 1) {
        l1_acc  += __shfl_down_sync(0xFFFFFFFFu, l1_acc,  o);
        vel_acc += __shfl_down_sync(0xFFFFFFFFu, vel_acc, o);
    }
    if (lane == 0) { s_red[0][wloc] = l1_acc; s_red[1][wloc] = vel_acc; }
    __syncthreads();

    // ---- block reduce + global accumulate + last-block finalize ----
    if (threadIdx.x == 0) {
        float a = 0.f, v = 0.f;
        #pragma unroll
        for (int i = 0; i < NWARP; i++) { a += s_red[0][i]; v += s_red[1][i]; }
        atomicAdd(&g_acc[0], (double)a);
        atomicAdd(&g_acc[1], (double)v);
        __threadfence();
        unsigned tk = atomicAdd(&g_ticket, 1u);
        s_last = (tk == gridDim.x - 1);
    }
    __syncthreads();

    if (s_last && threadIdx.x == 0) {
        double l1  = g_acc[0] / ((double)rows * (double)CH);
        double vel = g_acc[1] / ((double)rows * (double)(N_EDGES * 3));
        out[0] = (float)(l1 + 0.1 * vel);
        // reset persistent state so every graph replay starts identically
        g_acc[0] = 0.0;
        g_acc[1] = 0.0;
        __threadfence();
        atomicExch(&g_ticket, 0u);
    }
}

extern "C" void kernel_launch(void* const* d_in, const int* in_sizes, int n_in,
                              void* d_out, int out_size)
{
    const float* preds   = (const float*)d_in[0];
    const float* targets = (const float*)d_in[1];
    float* out = (float*)d_out;

    int n      = in_sizes[0];
    int rows   = n / CH;               // B*T = 131072
    int groups = rows / GROUP_ROWS;    // 4096

    cudaFuncSetAttribute(reg_loss_kernel,
                         cudaFuncAttributeMaxDynamicSharedMemorySize, SMEM_BYTES);

    // ONE launch: 296 blocks (2/SM, 77.3KB smem each), 16 warps per block
    reg_loss_kernel<<<296, THREADS, SMEM_BYTES>>>(preds, targets, out,
                                                  groups, rows);
}